// round 4
// baseline (speedup 1.0000x reference)
#include <cuda_runtime.h>
#include <math.h>

#define BB 16
#define CC 128
#define LL 16384
#define LK 4096
#define NH 8
#define DH 16

// ------------------- scratch (device globals; no allocations) -------------------
__device__ float g_dwq[BB*CC*LL];   // depthwise q out
__device__ float g_dwk[BB*CC*LK];
__device__ float g_dwv[BB*CC*LK];
__device__ float g_q  [BB*CC*LL];   // pointwise+gelu outs
__device__ float g_k  [BB*CC*LK];   // later normalized in-place (softmax over n)
__device__ float g_v  [BB*CC*LK];
__device__ float g_z  [BB*CC*LL];   // addw(mhlsa, x), pre-BN1
__device__ float g_pre[BB*CC*LL];   // addw(ffn, att_out), pre-BN2
__device__ float g_kv [BB*NH*DH*DH];
__device__ float g_weff[3*CC*CC];   // BN2d folded into pointwise W
__device__ float g_beff[3*CC];
__device__ float g_A1[CC], g_B1[CC], g_A2[CC], g_B2[CC];
// slots: 0/1 dwq sum/sumsq, 2/3 dwk, 4/5 dwv, 6/7 z, 8/9 pre
__device__ double g_stats[10*CC];

__device__ __forceinline__ float geluf(float x){
    return 0.5f * x * (1.0f + erff(x * 0.70710678118654752440f));
}
__device__ __forceinline__ float warpRedSum(float v){
    v += __shfl_xor_sync(0xffffffffu, v, 16);
    v += __shfl_xor_sync(0xffffffffu, v, 8);
    v += __shfl_xor_sync(0xffffffffu, v, 4);
    v += __shfl_xor_sync(0xffffffffu, v, 2);
    v += __shfl_xor_sync(0xffffffffu, v, 1);
    return v;
}

// ------------------- zero stats -------------------
__global__ void K_zero(){
    int i = blockIdx.x*256 + threadIdx.x;
    if (i < 10*CC) g_stats[i] = 0.0;
}

// ------------------- depthwise 3x3, 3 branches fused -------------------
// grid (2, C, B); block 256. Each block: rows [r0, r0+64) of the 128x128 map.
__global__ void K_dw(const float* __restrict__ x, const float* __restrict__ dw_w){
    __shared__ float im[66*128];
    int r0 = blockIdx.x*64, c = blockIdx.y, b = blockIdx.z;
    int tid = threadIdx.x;
    const float* xc = x + ((size_t)b*CC + c)*LL;
    #pragma unroll
    for (int i=0;i<33;i++){
        int e = i*256 + tid;
        int rr = e >> 7, w = e & 127;
        int gr = r0 - 1 + rr;
        im[e] = (gr >= 0 && gr < 128) ? xc[gr*128 + w] : 0.0f;
    }
    float wq[9], wk[9], wv[9];
    #pragma unroll
    for (int k=0;k<9;k++){
        wq[k] = dw_w[c*9 + k];
        wk[k] = dw_w[(CC   + c)*9 + k];
        wv[k] = dw_w[(2*CC + c)*9 + k];
    }
    __syncthreads();
    // q branch: stride 1, 64 rows x 128 cols
    float* outq = g_dwq + ((size_t)b*CC + c)*LL + r0*128;
    #pragma unroll 2
    for (int i=0;i<32;i++){
        int s = i*256 + tid;
        int hl = s >> 7, w = s & 127;
        float acc = 0.f;
        #pragma unroll
        for (int ky=0;ky<3;ky++){
            const float* row = im + (hl+ky)*128 + w;
            if (w > 0)   acc += wq[ky*3+0] * row[-1];
                         acc += wq[ky*3+1] * row[0];
            if (w < 127) acc += wq[ky*3+2] * row[1];
        }
        outq[s] = acc;
    }
    // k,v branches: stride 2, 32 rows x 64 cols
    float* outk = g_dwk + ((size_t)b*CC + c)*LK + (r0>>1)*64;
    float* outv = g_dwv + ((size_t)b*CC + c)*LK + (r0>>1)*64;
    #pragma unroll
    for (int i=0;i<8;i++){
        int s = i*256 + tid;
        int ho = s >> 6, wo = s & 63;
        float ak = 0.f, av = 0.f;
        #pragma unroll
        for (int ky=0;ky<3;ky++){
            const float* row = im + (2*ho+ky)*128 + 2*wo;
            if (wo > 0){ ak += wk[ky*3+0]*row[-1]; av += wv[ky*3+0]*row[-1]; }
            ak += wk[ky*3+1]*row[0]; av += wv[ky*3+1]*row[0];
            ak += wk[ky*3+2]*row[1]; av += wv[ky*3+2]*row[1];
        }
        outk[s] = ak; outv[s] = av;
    }
}

// ------------------- per-channel sum/sumsq stats -------------------
// which: 0 g_dwq, 1 g_dwk, 2 g_dwv, 3 g_z, 4 g_pre
// grid (C, B * (Lper/4096)); block 256, each block reduces 4096 elems.
__global__ void K_stats(int which, int Lper, int slot){
    const float* src = (which==0) ? g_dwq : (which==1) ? g_dwk :
                       (which==2) ? g_dwv : (which==3) ? g_z : g_pre;
    int c = blockIdx.x, j = blockIdx.y;
    int perB = Lper >> 12;
    int b = j / perB, lq = j - b*perB;
    const float* p = src + ((size_t)b*CC + c)*Lper + lq*4096;
    int tid = threadIdx.x;
    float s = 0.f, s2 = 0.f;
    #pragma unroll
    for (int i=0;i<16;i++){ float v = p[i*256 + tid]; s += v; s2 += v*v; }
    s = warpRedSum(s); s2 = warpRedSum(s2);
    __shared__ float r1[8], r2[8];
    int w = tid >> 5, ln = tid & 31;
    if (ln == 0){ r1[w] = s; r2[w] = s2; }
    __syncthreads();
    if (tid == 0){
        float a = 0.f, bq = 0.f;
        #pragma unroll
        for (int i=0;i<8;i++){ a += r1[i]; bq += r2[i]; }
        atomicAdd(&g_stats[(size_t)slot*CC + c],     (double)a);
        atomicAdd(&g_stats[(size_t)(slot+1)*CC + c], (double)bq);
    }
}

// ------------------- fold BN2d into pointwise weights -------------------
__global__ void K_prep(const float* __restrict__ bn2_g, const float* __restrict__ bn2_b,
                       const float* __restrict__ pw_w, const float* __restrict__ pw_b){
    __shared__ float alpha[CC], beta[CC];
    int t = threadIdx.x;  // 128
    for (int i=0;i<3;i++){
        double cnt = (i==0) ? (double)BB*(double)LL : (double)BB*(double)LK;
        double m = g_stats[(size_t)(2*i)*CC + t] / cnt;
        double v = g_stats[(size_t)(2*i+1)*CC + t] / cnt - m*m;
        float A = bn2_g[i*CC + t] * rsqrtf((float)v + 1e-5f);
        alpha[t] = A;
        beta[t]  = bn2_b[i*CC + t] - (float)m * A;
        __syncthreads();
        float acc = pw_b[i*CC + t];
        const float* wrow = pw_w   + (size_t)(i*CC + t)*CC;
        float*      werow = g_weff + (size_t)(i*CC + t)*CC;
        for (int c2=0;c2<CC;c2++){
            float w = wrow[c2];
            werow[c2] = w * alpha[c2];
            acc += w * beta[c2];
        }
        g_beff[i*CC + t] = acc;
        __syncthreads();
    }
}

// ------------------- pointwise GEMM (128x128) + bias + GELU -------------------
// grid (Ls/64, B); block 256; microtile 8 out x 4 cols; k chunked by 32.
__global__ void K_pw(int which, int Ls){
    const float* src = (which==0) ? g_dwq : (which==1) ? g_dwk : g_dwv;
    float*       dst = (which==0) ? g_q   : (which==1) ? g_k   : g_v;
    const float* W    = g_weff + which*CC*CC;
    const float* bias = g_beff + which*CC;

    __shared__ __align__(16) float Wsm[32*132];
    __shared__ __align__(16) float Xs[32*64];
    __shared__ float bs[128];
    int tid = threadIdx.x;
    int b = blockIdx.y, l0 = blockIdx.x*64;
    if (tid < 128) bs[tid] = bias[tid];
    int tx = tid & 15, ty = tid >> 4;
    float acc[8][4];
    #pragma unroll
    for (int i=0;i<8;i++)
        #pragma unroll
        for (int j=0;j<4;j++) acc[i][j] = 0.f;

    const float* srcb = src + (size_t)b*CC*Ls + l0;
    for (int k0=0;k0<128;k0+=32){
        __syncthreads();
        #pragma unroll
        for (int i=0;i<16;i++){
            int e = i*256 + tid;
            int o = e >> 5, kk = e & 31;
            Wsm[kk*132 + o] = W[o*128 + k0 + kk];
        }
        #pragma unroll
        for (int i=0;i<8;i++){
            int e = i*256 + tid;
            int rr = e >> 6, cc = e & 63;
            Xs[rr*64 + cc] = srcb[(size_t)(k0+rr)*Ls + cc];
        }
        __syncthreads();
        #pragma unroll
        for (int kk=0;kk<32;kk++){
            float4 w0 = *(const float4*)&Wsm[kk*132 + ty*8];
            float4 w1 = *(const float4*)&Wsm[kk*132 + ty*8 + 4];
            float4 xv = *(const float4*)&Xs[kk*64 + tx*4];
            float wa[8] = {w0.x,w0.y,w0.z,w0.w,w1.x,w1.y,w1.z,w1.w};
            float xa[4] = {xv.x,xv.y,xv.z,xv.w};
            #pragma unroll
            for (int i=0;i<8;i++)
                #pragma unroll
                for (int j=0;j<4;j++) acc[i][j] += wa[i]*xa[j];
        }
    }
    float* dstb = dst + (size_t)b*CC*Ls + l0;
    #pragma unroll
    for (int i=0;i<8;i++){
        int o = ty*8 + i;
        float bv = bs[o];
        float4 r;
        r.x = geluf(acc[i][0] + bv);
        r.y = geluf(acc[i][1] + bv);
        r.z = geluf(acc[i][2] + bv);
        r.w = geluf(acc[i][3] + bv);
        *(float4*)&dstb[(size_t)o*Ls + tx*4] = r;
    }
}

// ------------------- k softmax over sequence dim (in-place) -------------------
// grid (B*C); block 256; each block normalizes one row of 4096.
__global__ void K_ksoft(){
    float* row = g_k + (size_t)blockIdx.x * LK;
    int tid = threadIdx.x, w = tid >> 5, ln = tid & 31;
    float vals[16];
    float m = -1e30f;
    #pragma unroll
    for (int i=0;i<16;i++){ vals[i] = row[i*256 + tid]; m = fmaxf(m, vals[i]); }
    #pragma unroll
    for (int o=16;o>0;o>>=1) m = fmaxf(m, __shfl_xor_sync(0xffffffffu, m, o));
    __shared__ float rm[8], rs[8];
    if (ln == 0) rm[w] = m;
    __syncthreads();
    float bm = rm[0];
    #pragma unroll
    for (int i=1;i<8;i++) bm = fmaxf(bm, rm[i]);
    float s = 0.f;
    #pragma unroll
    for (int i=0;i<16;i++){ vals[i] = __expf(vals[i] - bm); s += vals[i]; }
    s = warpRedSum(s);
    if (ln == 0) rs[w] = s;
    __syncthreads();
    float tot = 0.f;
    #pragma unroll
    for (int i=0;i<8;i++) tot += rs[i];
    float inv = 1.f / tot;
    #pragma unroll
    for (int i=0;i<16;i++) row[i*256 + tid] = vals[i] * inv;
}

// ------------------- kv = ks^T @ v per (b,h): 16x16 over n=4096 -------------------
// grid (B*H); block 256; thread (d,e).
__global__ void K_kv(){
    __shared__ float ks[16*257], vs[16*257];
    int bh = blockIdx.x; int b = bh >> 3, h = bh & 7;
    int tid = threadIdx.x; int d = tid >> 4, e = tid & 15;
    const float* kb = g_k + ((size_t)b*CC + h*16)*LK;
    const float* vb = g_v + ((size_t)b*CC + h*16)*LK;
    float acc = 0.f;
    for (int n0=0;n0<LK;n0+=256){
        __syncthreads();
        #pragma unroll
        for (int i=0;i<16;i++){
            ks[i*257 + tid] = kb[(size_t)i*LK + n0 + tid];
            vs[i*257 + tid] = vb[(size_t)i*LK + n0 + tid];
        }
        __syncthreads();
        #pragma unroll 8
        for (int j=0;j<256;j++)
            acc += ks[d*257 + j] * vs[e*257 + j];
    }
    g_kv[((size_t)bh*16 + d)*16 + e] = acc;
}

// ------------------- attention apply + residual addw -> g_z -------------------
// grid (L/128, B); block 128; thread-per-token.
__global__ void K_att(const float* __restrict__ x, const float* __restrict__ add_w){
    __shared__ float kvs[NH*DH*DH];
    int b = blockIdx.y;
    int tid = threadIdx.x;
    int l = blockIdx.x*128 + tid;
    for (int i=tid;i<NH*DH*DH;i+=128) kvs[i] = g_kv[(size_t)b*NH*DH*DH + i];
    __syncthreads();
    float a0 = fmaxf(add_w[0], 0.f), a1 = fmaxf(add_w[1], 0.f);
    float inv = 1.f / (a0 + a1 + 1e-12f);
    float w0 = a0*inv, w1 = a1*inv;
    const float* qb = g_q + (size_t)b*CC*LL + l;
    const float* xb = x   + (size_t)b*CC*LL + l;
    float*       zb = g_z + (size_t)b*CC*LL + l;
    for (int h=0;h<NH;h++){
        float qv[16]; float m = -1e30f;
        #pragma unroll
        for (int d=0;d<16;d++){ qv[d] = qb[(size_t)(h*16+d)*LL]; m = fmaxf(m, qv[d]); }
        float s = 0.f;
        #pragma unroll
        for (int d=0;d<16;d++){ qv[d] = __expf(qv[d] - m); s += qv[d]; }
        float is = 1.f / s;
        const float* kvh = kvs + h*256;
        #pragma unroll
        for (int e=0;e<16;e++){
            float acc = 0.f;
            #pragma unroll
            for (int d=0;d<16;d++) acc += qv[d]*kvh[d*16 + e];
            acc *= is;
            zb[(size_t)(h*16+e)*LL] = w0*acc + w1*xb[(size_t)(h*16+e)*LL];
        }
    }
}

// ------------------- BN1d affine coefficients -------------------
// sel 0: slot 6 -> g_A1/g_B1 ; sel 1: slot 8 -> g_A2/g_B2. <<<1,128>>>
__global__ void K_bnaff(int sel, const float* __restrict__ g, const float* __restrict__ bt){
    int t = threadIdx.x;
    int slot = sel ? 8 : 6;
    double cnt = (double)BB * (double)LL;
    double m = g_stats[(size_t)slot*CC + t] / cnt;
    double v = g_stats[(size_t)(slot+1)*CC + t] / cnt - m*m;
    float a = g[t] * rsqrtf((float)v + 1e-5f);
    float bc = bt[t] - (float)m * a;
    if (sel){ g_A2[t] = a; g_B2[t] = bc; }
    else    { g_A1[t] = a; g_B1[t] = bc; }
}

// ------------------- FFN (128->32->128) + residual addw -> g_pre -------------------
// grid (L/128, B); block 128; thread-per-token; att_out computed on the fly from g_z.
__global__ void K_ffn(const float* __restrict__ W1, const float* __restrict__ b1,
                      const float* __restrict__ W2, const float* __restrict__ b2,
                      const float* __restrict__ fw){
    __shared__ float W1s[128*32];
    __shared__ float W2s[32*128];
    __shared__ float b1s[32];
    __shared__ float b2s[128];
    int tid = threadIdx.x;
    int b = blockIdx.y;
    int l = blockIdx.x*128 + tid;
    for (int i=tid;i<4096;i+=128){ W1s[i] = W1[i]; W2s[i] = W2[i]; }
    if (tid < 32) b1s[tid] = b1[tid];
    b2s[tid] = b2[tid];
    __syncthreads();
    float a0 = fmaxf(fw[0], 0.f), a1 = fmaxf(fw[1], 0.f);
    float inv = 1.f / (a0 + a1 + 1e-12f);
    float w0 = a0*inv, w1 = a1*inv;
    const float* zb = g_z   + (size_t)b*CC*LL + l;
    float*       pb = g_pre + (size_t)b*CC*LL + l;
    float h[32];
    #pragma unroll
    for (int f=0;f<32;f++) h[f] = b1s[f];
    for (int c=0;c<128;c++){
        float xv = g_A1[c]*zb[(size_t)c*LL] + g_B1[c];
        #pragma unroll
        for (int f=0;f<32;f++) h[f] += W1s[c*32 + f] * xv;
    }
    #pragma unroll
    for (int f=0;f<32;f++) h[f] = geluf(h[f]);
    for (int o=0;o<128;o++){
        float acc = b2s[o];
        #pragma unroll
        for (int f=0;f<32;f++) acc += W2s[f*128 + o] * h[f];
        float y = geluf(acc);
        float ao = g_A1[o]*zb[(size_t)o*LL] + g_B1[o];
        pb[(size_t)o*LL] = w0*y + w1*ao;
    }
}

// ------------------- final BN affine -> d_out -------------------
__global__ void K_final(float* __restrict__ out){
    size_t i = ((size_t)blockIdx.x*256 + threadIdx.x)*4;
    int c = (int)((i >> 14) & 127);
    float4 v = *(const float4*)&g_pre[i];
    float A = g_A2[c], Bc = g_B2[c];
    float4 r;
    r.x = A*v.x + Bc; r.y = A*v.y + Bc; r.z = A*v.z + Bc; r.w = A*v.w + Bc;
    *(float4*)&out[i] = r;
}

// ------------------- launch -------------------
extern "C" void kernel_launch(void* const* d_in, const int* in_sizes, int n_in,
                              void* d_out, int out_size){
    const float* x         = (const float*)d_in[0];
    const float* dw_w      = (const float*)d_in[1];
    const float* bn2_g     = (const float*)d_in[2];
    const float* bn2_b     = (const float*)d_in[3];
    const float* pw_w      = (const float*)d_in[4];
    const float* pw_b      = (const float*)d_in[5];
    const float* add_w     = (const float*)d_in[6];
    const float* bn1_g     = (const float*)d_in[7];
    const float* bn1_b     = (const float*)d_in[8];
    const float* W1        = (const float*)d_in[9];
    const float* b1        = (const float*)d_in[10];
    const float* W2        = (const float*)d_in[11];
    const float* b2        = (const float*)d_in[12];
    const float* ffn_add_w = (const float*)d_in[13];
    const float* ffn_bn_g  = (const float*)d_in[14];
    const float* ffn_bn_b  = (const float*)d_in[15];
    float* out = (float*)d_out;

    K_zero<<<5,256>>>();
    K_dw<<<dim3(2,CC,BB),256>>>(x, dw_w);
    K_stats<<<dim3(CC,64),256>>>(0, LL, 0);
    K_stats<<<dim3(CC,16),256>>>(1, LK, 2);
    K_stats<<<dim3(CC,16),256>>>(2, LK, 4);
    K_prep<<<1,128>>>(bn2_g, bn2_b, pw_w, pw_b);
    K_pw<<<dim3(LL/64,BB),256>>>(0, LL);
    K_pw<<<dim3(LK/64,BB),256>>>(1, LK);
    K_pw<<<dim3(LK/64,BB),256>>>(2, LK);
    K_ksoft<<<BB*CC,256>>>();
    K_kv<<<BB*NH,256>>>();
    K_att<<<dim3(LL/128,BB),128>>>(x, add_w);
    K_stats<<<dim3(CC,64),256>>>(3, LL, 6);
    K_bnaff<<<1,128>>>(0, bn1_g, bn1_b);
    K_ffn<<<dim3(LL/128,BB),128>>>(W1, b1, W2, b2, ffn_add_w);
    K_stats<<<dim3(CC,64),256>>>(4, LL, 8);
    K_bnaff<<<1,128>>>(1, ffn_bn_g, ffn_bn_b);
    K_final<<<(BB*CC*LL)/(256*4),256>>>(out);
}

// round 7
// speedup vs baseline: 1.1115x; 1.1115x over previous
#include <cuda_runtime.h>
#include <math.h>

#define BB 16
#define CC 128
#define LL 16384
#define LK 4096
#define NH 8
#define DH 16

typedef unsigned long long ull;

// ------------------- scratch (device globals; no allocations) -------------------
__device__ float g_dwq[BB*CC*LL];
__device__ float g_dwk[BB*CC*LK];
__device__ float g_dwv[BB*CC*LK];
__device__ float g_k  [BB*CC*LK];
__device__ float g_v  [BB*CC*LK];
__device__ float g_z  [BB*CC*LL];
__device__ float g_pre[BB*CC*LL];
__device__ float g_kv [BB*NH*DH*DH];
__device__ float g_km [BB*CC];
__device__ float g_kis[BB*CC];
__device__ float g_weff[3*CC*CC];
__device__ float g_beff[3*CC];
__device__ float g_A1[CC], g_B1[CC], g_A2[CC], g_B2[CC];
// slots: 0/1 dwq, 2/3 dwk, 4/5 dwv, 6/7 z, 8/9 pre
__device__ double g_stats[10*CC];

// ------------------- helpers -------------------
__device__ __forceinline__ float geluf(float x){
    return 0.5f * x * (1.0f + erff(x * 0.70710678118654752440f));
}
__device__ __forceinline__ float warpRedSum(float v){
    v += __shfl_xor_sync(0xffffffffu, v, 16);
    v += __shfl_xor_sync(0xffffffffu, v, 8);
    v += __shfl_xor_sync(0xffffffffu, v, 4);
    v += __shfl_xor_sync(0xffffffffu, v, 2);
    v += __shfl_xor_sync(0xffffffffu, v, 1);
    return v;
}
__device__ __forceinline__ ull pack2(float lo, float hi){
    ull r; unsigned a = __float_as_uint(lo), b = __float_as_uint(hi);
    asm("mov.b64 %0, {%1,%2};" : "=l"(r) : "r"(a), "r"(b));
    return r;
}
__device__ __forceinline__ void unpack2(ull v, float& lo, float& hi){
    unsigned a, b;
    asm("mov.b64 {%0,%1}, %2;" : "=r"(a), "=r"(b) : "l"(v));
    lo = __uint_as_float(a); hi = __uint_as_float(b);
}
__device__ __forceinline__ ull fma2(ull a, ull b, ull c){
    ull d;
    asm("fma.rn.f32x2 %0, %1, %2, %3;" : "=l"(d) : "l"(a), "l"(b), "l"(c));
    return d;
}

__device__ __forceinline__ void blockAccum(float v, double* dst, float* red){
    v = warpRedSum(v);
    int w = threadIdx.x >> 5, ln = threadIdx.x & 31;
    if (ln == 0) red[w] = v;
    __syncthreads();
    if (threadIdx.x == 0){
        float s = 0.f;
        #pragma unroll
        for (int i=0;i<8;i++) s += red[i];
        atomicAdd(dst, (double)s);
    }
    __syncthreads();
}

// ------------------- zero stats -------------------
__global__ void K_zero(){
    int i = blockIdx.x*256 + threadIdx.x;
    if (i < 10*CC) g_stats[i] = 0.0;
}

// ------------------- depthwise 3x3, 3 branches + fused BN stats -------------------
// grid (2, C, B); block 256.
__global__ void K_dw(const float* __restrict__ x, const float* __restrict__ dw_w){
    __shared__ float im[66*128];
    __shared__ float red[8];
    int r0 = blockIdx.x*64, c = blockIdx.y, b = blockIdx.z;
    int tid = threadIdx.x;
    const float* xc = x + ((size_t)b*CC + c)*LL;
    #pragma unroll
    for (int i=0;i<33;i++){
        int e = i*256 + tid;
        int rr = e >> 7, w = e & 127;
        int gr = r0 - 1 + rr;
        im[e] = (gr >= 0 && gr < 128) ? xc[gr*128 + w] : 0.0f;
    }
    float wq[9], wk[9], wv[9];
    #pragma unroll
    for (int k=0;k<9;k++){
        wq[k] = dw_w[c*9 + k];
        wk[k] = dw_w[(CC   + c)*9 + k];
        wv[k] = dw_w[(2*CC + c)*9 + k];
    }
    __syncthreads();
    float sq=0.f, sq2=0.f, sk=0.f, sk2=0.f, sv=0.f, sv2=0.f;
    float* outq = g_dwq + ((size_t)b*CC + c)*LL + r0*128;
    #pragma unroll 2
    for (int i=0;i<32;i++){
        int s = i*256 + tid;
        int hl = s >> 7, w = s & 127;
        float acc = 0.f;
        #pragma unroll
        for (int ky=0;ky<3;ky++){
            const float* row = im + (hl+ky)*128 + w;
            if (w > 0)   acc += wq[ky*3+0] * row[-1];
                         acc += wq[ky*3+1] * row[0];
            if (w < 127) acc += wq[ky*3+2] * row[1];
        }
        outq[s] = acc;
        sq += acc; sq2 += acc*acc;
    }
    float* outk = g_dwk + ((size_t)b*CC + c)*LK + (r0>>1)*64;
    float* outv = g_dwv + ((size_t)b*CC + c)*LK + (r0>>1)*64;
    #pragma unroll
    for (int i=0;i<8;i++){
        int s = i*256 + tid;
        int ho = s >> 6, wo = s & 63;
        float ak = 0.f, av = 0.f;
        #pragma unroll
        for (int ky=0;ky<3;ky++){
            const float* row = im + (2*ho+ky)*128 + 2*wo;
            if (wo > 0){ ak += wk[ky*3+0]*row[-1]; av += wv[ky*3+0]*row[-1]; }
            ak += wk[ky*3+1]*row[0]; av += wv[ky*3+1]*row[0];
            ak += wk[ky*3+2]*row[1]; av += wv[ky*3+2]*row[1];
        }
        outk[s] = ak; outv[s] = av;
        sk += ak; sk2 += ak*ak; sv += av; sv2 += av*av;
    }
    __syncthreads();
    blockAccum(sq,  &g_stats[0*CC + c], red);
    blockAccum(sq2, &g_stats[1*CC + c], red);
    blockAccum(sk,  &g_stats[2*CC + c], red);
    blockAccum(sk2, &g_stats[3*CC + c], red);
    blockAccum(sv,  &g_stats[4*CC + c], red);
    blockAccum(sv2, &g_stats[5*CC + c], red);
}

// ------------------- fold BN2d into pointwise weights -------------------
__global__ void K_prep(const float* __restrict__ bn2_g, const float* __restrict__ bn2_b,
                       const float* __restrict__ pw_w, const float* __restrict__ pw_b){
    __shared__ float alpha[CC], beta[CC];
    int t = threadIdx.x;  // 128
    for (int i=0;i<3;i++){
        double cnt = (i==0) ? (double)BB*(double)LL : (double)BB*(double)LK;
        double m = g_stats[(size_t)(2*i)*CC + t] / cnt;
        double v = g_stats[(size_t)(2*i+1)*CC + t] / cnt - m*m;
        float A = bn2_g[i*CC + t] * rsqrtf((float)v + 1e-5f);
        alpha[t] = A;
        beta[t]  = bn2_b[i*CC + t] - (float)m * A;
        __syncthreads();
        float acc = pw_b[i*CC + t];
        const float* wrow = pw_w   + (size_t)(i*CC + t)*CC;
        float*      werow = g_weff + (size_t)(i*CC + t)*CC;
        for (int c2=0;c2<CC;c2++){
            float w = wrow[c2];
            werow[c2] = w * alpha[c2];
            acc += w * beta[c2];
        }
        g_beff[i*CC + t] = acc;
        __syncthreads();
    }
}

// ------------------- shared 128x128 GEMM mainloop (f32x2) -------------------
// block tile: 128 outs x 128 cols, 256 threads, microtile 8x8.
__device__ __forceinline__ void gemm128(const float* __restrict__ W,
                                        const float* __restrict__ srcb, int Ls,
                                        float* Wsm, float* Xs, ull acc[8][4]){
    int tid = threadIdx.x, tx = tid & 15, ty = tid >> 4;
    for (int k0=0;k0<128;k0+=32){
        __syncthreads();
        #pragma unroll
        for (int i=0;i<16;i++){
            int e = i*256 + tid;
            int o = e >> 5, kk = e & 31;
            Wsm[kk*132 + o] = W[o*128 + k0 + kk];
        }
        #pragma unroll
        for (int i=0;i<16;i++){
            int e = i*256 + tid;
            Xs[e] = srcb[(size_t)(k0 + (e>>7))*Ls + (e & 127)];
        }
        __syncthreads();
        #pragma unroll
        for (int kk=0;kk<32;kk++){
            const float* wr = &Wsm[kk*132 + ty*8];
            float4 w0 = *(const float4*)wr;
            float4 w1 = *(const float4*)(wr + 4);
            ull wp[8] = { pack2(w0.x,w0.x), pack2(w0.y,w0.y), pack2(w0.z,w0.z), pack2(w0.w,w0.w),
                          pack2(w1.x,w1.x), pack2(w1.y,w1.y), pack2(w1.z,w1.z), pack2(w1.w,w1.w) };
            const ulonglong2* xr = (const ulonglong2*)&Xs[kk*128 + tx*8];
            ulonglong2 xa = xr[0], xb = xr[1];
            #pragma unroll
            for (int i=0;i<8;i++){
                acc[i][0] = fma2(wp[i], xa.x, acc[i][0]);
                acc[i][1] = fma2(wp[i], xa.y, acc[i][1]);
                acc[i][2] = fma2(wp[i], xb.x, acc[i][2]);
                acc[i][3] = fma2(wp[i], xb.y, acc[i][3]);
            }
        }
    }
}

// ------------------- pointwise GEMM for k/v + bias + GELU -------------------
// grid (LK/128, B)
__global__ void K_pw(int which){
    __shared__ __align__(16) float Wsm[32*132];
    __shared__ __align__(16) float Xs[32*128];
    const float* src  = (which==1) ? g_dwk : g_dwv;
    float*       dst  = (which==1) ? g_k   : g_v;
    const float* W    = g_weff + which*CC*CC;
    const float* bias = g_beff + which*CC;
    int b = blockIdx.y, l0 = blockIdx.x*128;
    ull acc[8][4];
    #pragma unroll
    for (int i=0;i<8;i++)
        #pragma unroll
        for (int j=0;j<4;j++) acc[i][j] = 0ULL;
    gemm128(W, src + ((size_t)b*CC)*LK + l0, LK, Wsm, Xs, acc);
    int tid = threadIdx.x, tx = tid & 15, ty = tid >> 4;
    float* dstb = dst + ((size_t)b*CC)*LK + l0;
    #pragma unroll
    for (int i=0;i<8;i++){
        int o = ty*8 + i;
        float bv = bias[o];
        float v[8];
        unpack2(acc[i][0], v[0], v[1]);
        unpack2(acc[i][1], v[2], v[3]);
        unpack2(acc[i][2], v[4], v[5]);
        unpack2(acc[i][3], v[6], v[7]);
        float4 r0, r1;
        r0.x = geluf(v[0]+bv); r0.y = geluf(v[1]+bv); r0.z = geluf(v[2]+bv); r0.w = geluf(v[3]+bv);
        r1.x = geluf(v[4]+bv); r1.y = geluf(v[5]+bv); r1.z = geluf(v[6]+bv); r1.w = geluf(v[7]+bv);
        *(float4*)&dstb[(size_t)o*LK + tx*8]     = r0;
        *(float4*)&dstb[(size_t)o*LK + tx*8 + 4] = r1;
    }
}

// ------------------- per-row max + sum(exp) of k -------------------
// grid (B*C); block 256.
__global__ void K_krow(){
    int row = blockIdx.x;
    const float* p = g_k + (size_t)row*LK;
    int tid = threadIdx.x, w = tid >> 5, ln = tid & 31;
    float vals[16], m = -1e30f;
    #pragma unroll
    for (int i=0;i<16;i++){ vals[i] = p[i*256 + tid]; m = fmaxf(m, vals[i]); }
    #pragma unroll
    for (int o=16;o>0;o>>=1) m = fmaxf(m, __shfl_xor_sync(0xffffffffu, m, o));
    __shared__ float rm[8], rs[8];
    if (ln == 0) rm[w] = m;
    __syncthreads();
    float bm = rm[0];
    #pragma unroll
    for (int i=1;i<8;i++) bm = fmaxf(bm, rm[i]);
    float s = 0.f;
    #pragma unroll
    for (int i=0;i<16;i++) s += __expf(vals[i] - bm);
    s = warpRedSum(s);
    if (ln == 0) rs[w] = s;
    __syncthreads();
    if (tid == 0){
        float tot = 0.f;
        #pragma unroll
        for (int i=0;i<8;i++) tot += rs[i];
        g_km[row]  = bm;
        g_kis[row] = 1.f / tot;
    }
}

// ------------------- kv = softmax_n(k)^T @ v per (b,h) -------------------
// grid (B*H); block 256.
__global__ void K_kv(){
    __shared__ float ks[16*257], vs[16*257];
    __shared__ float mrow[16], isrow[16];
    int bh = blockIdx.x; int b = bh >> 3, h = bh & 7;
    int tid = threadIdx.x; int d = tid >> 4, e = tid & 15;
    const float* kb = g_k + ((size_t)b*CC + h*16)*LK;
    const float* vb = g_v + ((size_t)b*CC + h*16)*LK;
    if (tid < 16){
        mrow[tid]  = g_km [b*CC + h*16 + tid];
        isrow[tid] = g_kis[b*CC + h*16 + tid];
    }
    __syncthreads();
    float acc = 0.f;
    for (int n0=0;n0<LK;n0+=256){
        __syncthreads();
        #pragma unroll
        for (int i=0;i<16;i++){
            ks[i*257 + tid] = __expf(kb[(size_t)i*LK + n0 + tid] - mrow[i]) * isrow[i];
            vs[i*257 + tid] = vb[(size_t)i*LK + n0 + tid];
        }
        __syncthreads();
        #pragma unroll 8
        for (int j=0;j<256;j++)
            acc += ks[d*257 + j] * vs[e*257 + j];
    }
    g_kv[((size_t)bh*16 + d)*16 + e] = acc;
}

// ------------------- q GEMM + GELU + attention + residual + z-stats -------------------
// grid (LL/128, B); block 256; dynamic smem.
__global__ void K_pwatt(const float* __restrict__ x, const float* __restrict__ add_w){
    extern __shared__ float dsm[];
    float* Wsm = dsm;            // 4224 floats
    float* Xs  = dsm + 4224;     // 4096 floats
    float* Qs  = dsm;            // 128*132 = 16896 floats (reuses Wsm/Xs region)
    float* kvs = dsm + 16896;    // 2048 floats
    int tid = threadIdx.x;
    int b = blockIdx.y, l0 = blockIdx.x*128;
    {
        const float* kvp = g_kv + (size_t)b*NH*DH*DH;
        for (int i=tid;i<NH*DH*DH;i+=256) kvs[i] = kvp[i];
    }
    ull acc[8][4];
    #pragma unroll
    for (int i=0;i<8;i++)
        #pragma unroll
        for (int j=0;j<4;j++) acc[i][j] = 0ULL;
    gemm128(g_weff, g_dwq + ((size_t)b*CC)*LL + l0, LL, Wsm, Xs, acc);
    __syncthreads();
    int tx = tid & 15, ty = tid >> 4;
    #pragma unroll
    for (int i=0;i<8;i++){
        int o = ty*8 + i;
        float bv = g_beff[o];
        float v[8];
        unpack2(acc[i][0], v[0], v[1]);
        unpack2(acc[i][1], v[2], v[3]);
        unpack2(acc[i][2], v[4], v[5]);
        unpack2(acc[i][3], v[6], v[7]);
        float4 r0, r1;
        r0.x = geluf(v[0]+bv); r0.y = geluf(v[1]+bv); r0.z = geluf(v[2]+bv); r0.w = geluf(v[3]+bv);
        r1.x = geluf(v[4]+bv); r1.y = geluf(v[5]+bv); r1.z = geluf(v[6]+bv); r1.w = geluf(v[7]+bv);
        *(float4*)&Qs[o*132 + tx*8]     = r0;
        *(float4*)&Qs[o*132 + tx*8 + 4] = r1;
    }
    __syncthreads();
    // attention: thread handles token l for 4 heads
    {
        int l = tid & 127, hb = (tid >> 7) * 4;
        #pragma unroll
        for (int hh=0;hh<4;hh++){
            int h = hb + hh;
            float qv[16], m = -1e30f;
            #pragma unroll
            for (int d=0;d<16;d++){ qv[d] = Qs[(h*16+d)*132 + l]; m = fmaxf(m, qv[d]); }
            float s = 0.f;
            #pragma unroll
            for (int d=0;d<16;d++){ qv[d] = __expf(qv[d] - m); s += qv[d]; }
            float is = 1.f / s;
            const float* kvh = kvs + h*256;
            float av[16];
            #pragma unroll
            for (int e=0;e<16;e++) av[e] = 0.f;
            #pragma unroll
            for (int d=0;d<16;d++){
                float q = qv[d];
                #pragma unroll
                for (int e=0;e<16;e++) av[e] += q * kvh[d*16 + e];
            }
            #pragma unroll
            for (int e=0;e<16;e++) Qs[(h*16+e)*132 + l] = av[e] * is;
        }
    }
    __syncthreads();
    // residual addw + writeout + store z into Qs for stats
    float a0 = fmaxf(add_w[0], 0.f), a1 = fmaxf(add_w[1], 0.f);
    float inv = 1.f / (a0 + a1 + 1e-12f);
    float w0 = a0*inv, w1 = a1*inv;
    const float* xb = x   + ((size_t)b*CC)*LL + l0;
    float*       zb = g_z + ((size_t)b*CC)*LL + l0;
    #pragma unroll 4
    for (int i=0;i<64;i++){
        int e = i*256 + tid;
        int c = e >> 7, lc = e & 127;
        float att = Qs[c*132 + lc];
        float zv = w0*att + w1*xb[(size_t)c*LL + lc];
        zb[(size_t)c*LL + lc] = zv;
        Qs[c*132 + lc] = zv;
    }
    __syncthreads();
    if (tid < 128){
        float s = 0.f, s2 = 0.f;
        #pragma unroll 8
        for (int j=0;j<128;j++){ float v = Qs[tid*132 + j]; s += v; s2 += v*v; }
        atomicAdd(&g_stats[6*CC + tid], (double)s);
        atomicAdd(&g_stats[7*CC + tid], (double)s2);
    }
}

// ------------------- BN1d affine coefficients -------------------
__global__ void K_bnaff(int sel, const float* __restrict__ g, const float* __restrict__ bt){
    int t = threadIdx.x;
    int slot = sel ? 8 : 6;
    double cnt = (double)BB * (double)LL;
    double m = g_stats[(size_t)slot*CC + t] / cnt;
    double v = g_stats[(size_t)(slot+1)*CC + t] / cnt - m*m;
    float a = g[t] * rsqrtf((float)v + 1e-5f);
    float bc = bt[t] - (float)m * a;
    if (sel){ g_A2[t] = a; g_B2[t] = bc; }
    else    { g_A1[t] = a; g_B1[t] = bc; }
}

// ------------------- FFN (128->32->128) f32x2 + residual addw -> g_pre -------------------
// grid (LL/256, B); block 256; one token per thread.
__global__ void K_ffn(const float* __restrict__ W1, const float* __restrict__ b1,
                      const float* __restrict__ W2, const float* __restrict__ b2,
                      const float* __restrict__ fw){
    __shared__ __align__(16) float W1s[128*32];
    __shared__ __align__(16) float W2s[32*128];
    __shared__ float b1s[32], b2s[128], sA[128], sB[128];
    int tid = threadIdx.x;
    int b = blockIdx.y;
    int l = blockIdx.x*256 + tid;
    #pragma unroll
    for (int i=0;i<16;i++){ W1s[i*256 + tid] = W1[i*256 + tid]; W2s[i*256 + tid] = W2[i*256 + tid]; }
    if (tid < 32) b1s[tid] = b1[tid];
    if (tid < 128){ b2s[tid] = b2[tid]; sA[tid] = g_A1[tid]; sB[tid] = g_B1[tid]; }
    __syncthreads();
    float a0 = fmaxf(fw[0], 0.f), a1 = fmaxf(fw[1], 0.f);
    float inv = 1.f / (a0 + a1 + 1e-12f);
    float w0 = a0*inv, w1 = a1*inv;
    const float* zb = g_z   + ((size_t)b*CC)*LL + l;
    float*       pb = g_pre + ((size_t)b*CC)*LL + l;
    // phase A: h = W1^T xin + b1 (packed over f pairs)
    ull hp[16];
    #pragma unroll
    for (int j=0;j<16;j++) hp[j] = pack2(b1s[2*j], b1s[2*j+1]);
    for (int c=0;c<128;c++){
        float xv = sA[c]*zb[(size_t)c*LL] + sB[c];
        ull xp = pack2(xv, xv);
        const ull* wr = (const ull*)&W1s[c*32];
        #pragma unroll
        for (int j=0;j<16;j++) hp[j] = fma2(wr[j], xp, hp[j]);
    }
    // gelu + broadcast-pack
    ull hbp[32];
    #pragma unroll
    for (int j=0;j<16;j++){
        float ha, hb2;
        unpack2(hp[j], ha, hb2);
        ha = geluf(ha); hb2 = geluf(hb2);
        hbp[2*j]   = pack2(ha, ha);
        hbp[2*j+1] = pack2(hb2, hb2);
    }
    // phase B: out = W2^T h + b2 (packed over o pairs), 8 outs at a time
    for (int og=0;og<16;og++){
        int o0 = og*8;
        ull a0p = pack2(b2s[o0],   b2s[o0+1]);
        ull a1p = pack2(b2s[o0+2], b2s[o0+3]);
        ull a2p = pack2(b2s[o0+4], b2s[o0+5]);
        ull a3p = pack2(b2s[o0+6], b2s[o0+7]);
        #pragma unroll
        for (int f=0;f<32;f++){
            const ulonglong2* wr = (const ulonglong2*)&W2s[f*128 + o0];
            ulonglong2 wa = wr[0], wb = wr[1];
            a0p = fma2(wa.x, hbp[f], a0p);
            a1p = fma2(wa.y, hbp[f], a1p);
            a2p = fma2(wb.x, hbp[f], a2p);
            a3p = fma2(wb.y, hbp[f], a3p);
        }
        float y[8];
        unpack2(a0p, y[0], y[1]);
        unpack2(a1p, y[2], y[3]);
        unpack2(a2p, y[4], y[5]);
        unpack2(a3p, y[6], y[7]);
        #pragma unroll
        for (int j=0;j<8;j++){
            int o = o0 + j;
            float yv = geluf(y[j]);
            float ao = sA[o]*zb[(size_t)o*LL] + sB[o];
            pb[(size_t)o*LL] = w0*yv + w1*ao;
        }
    }
}

// ------------------- stats for g_pre -------------------
// grid (C, 64); block 256.
__global__ void K_statsP(){
    int c = blockIdx.x, j = blockIdx.y;
    int b = j >> 2, lq = j & 3;
    const float* p = g_pre + ((size_t)b*CC + c)*LL + lq*4096;
    int tid = threadIdx.x;
    float s = 0.f, s2 = 0.f;
    #pragma unroll
    for (int i=0;i<16;i++){ float v = p[i*256 + tid]; s += v; s2 += v*v; }
    s = warpRedSum(s); s2 = warpRedSum(s2);
    __shared__ float r1[8], r2[8];
    int w = tid >> 5, ln = tid & 31;
    if (ln == 0){ r1[w] = s; r2[w] = s2; }
    __syncthreads();
    if (tid == 0){
        float a = 0.f, bq = 0.f;
        #pragma unroll
        for (int i=0;i<8;i++){ a += r1[i]; bq += r2[i]; }
        atomicAdd(&g_stats[8*CC + c], (double)a);
        atomicAdd(&g_stats[9*CC + c], (double)bq);
    }
}

// ------------------- final BN affine -> d_out -------------------
__global__ void K_final(float* __restrict__ out){
    size_t i = ((size_t)blockIdx.x*256 + threadIdx.x)*4;
    int c = (int)((i >> 14) & 127);
    float4 v = *(const float4*)&g_pre[i];
    float A = g_A2[c], Bc = g_B2[c];
    float4 r;
    r.x = A*v.x + Bc; r.y = A*v.y + Bc; r.z = A*v.z + Bc; r.w = A*v.w + Bc;
    *(float4*)&out[i] = r;
}

// ------------------- launch -------------------
extern "C" void kernel_launch(void* const* d_in, const int* in_sizes, int n_in,
                              void* d_out, int out_size){
    const float* x         = (const float*)d_in[0];
    const float* dw_w      = (const float*)d_in[1];
    const float* bn2_g     = (const float*)d_in[2];
    const float* bn2_b     = (const float*)d_in[3];
    const float* pw_w      = (const float*)d_in[4];
    const float* pw_b      = (const float*)d_in[5];
    const float* add_w     = (const float*)d_in[6];
    const float* bn1_g     = (const float*)d_in[7];
    const float* bn1_b     = (const float*)d_in[8];
    const float* W1        = (const float*)d_in[9];
    const float* b1        = (const float*)d_in[10];
    const float* W2        = (const float*)d_in[11];
    const float* b2        = (const float*)d_in[12];
    const float* ffn_add_w = (const float*)d_in[13];
    const float* ffn_bn_g  = (const float*)d_in[14];
    const float* ffn_bn_b  = (const float*)d_in[15];
    float* out = (float*)d_out;

    const int PWATT_SMEM = (16896 + 2048) * 4;  // 75776 bytes
    cudaFuncSetAttribute(K_pwatt, cudaFuncAttributeMaxDynamicSharedMemorySize, PWATT_SMEM);

    K_zero<<<5,256>>>();
    K_dw<<<dim3(2,CC,BB),256>>>(x, dw_w);
    K_prep<<<1,128>>>(bn2_g, bn2_b, pw_w, pw_b);
    K_pw<<<dim3(LK/128,BB),256>>>(1);
    K_pw<<<dim3(LK/128,BB),256>>>(2);
    K_krow<<<BB*CC,256>>>();
    K_kv<<<BB*NH,256>>>();
    K_pwatt<<<dim3(LL/128,BB),256,PWATT_SMEM>>>(x, add_w);
    K_bnaff<<<1,128>>>(0, bn1_g, bn1_b);
    K_ffn<<<dim3(LL/256,BB),256>>>(W1, b1, W2, b2, ffn_add_w);
    K_statsP<<<dim3(CC,64),256>>>();
    K_bnaff<<<1,128>>>(1, ffn_bn_g, ffn_bn_b);
    K_final<<<(BB*CC*LL)/(256*4),256>>>(out);
}